// round 2
// baseline (speedup 1.0000x reference)
#include <cuda_runtime.h>
#include <math.h>

#define NROWS   12800     // B*C
#define BATCH   256
#define CDIM    50
#define INPUT   128
#define INTER   64
#define HIDDEN  128
#define NSLOT   11
#define USTRIDE (NSLOT * INTER)   // 704

// Bucketed accumulator: u[b][dist_slot][j], fp32. 720 KB static device scratch.
__device__ float g_u[BATCH * NSLOT * INTER];

// ---------------------------------------------------------------------------
// K0: zero the accumulator (must happen every launch; graph-capturable kernel)
// ---------------------------------------------------------------------------
__global__ void zero_u_kernel() {
    int n = BATCH * NSLOT * INTER;
    for (int i = blockIdx.x * blockDim.x + threadIdx.x; i < n;
         i += gridDim.x * blockDim.x)
        g_u[i] = 0.0f;
}

// ---------------------------------------------------------------------------
// K1: slot-major stage 1.
// grid.x = time slot s (11), grid.y = row-range chunk.
// CTA loads tw[s] (128x64 fp32 = 32KB) into smem once; each warp scans rows,
// processes rows with time==s && mask, computes t = x_row @ tw[s]
// (2 outputs per lane), atomicAdds into g_u[b][dist][*].
// ---------------------------------------------------------------------------
__global__ __launch_bounds__(256) void stage1_kernel(
    const float* __restrict__ x,          // (B,C,INPUT)
    const int* __restrict__ tc,           // (B,C)
    const int* __restrict__ dc,           // (B,C)
    const int* __restrict__ mask,         // (B,C) bool promoted to int32
    const float* __restrict__ tw)         // (NSLOT, INPUT, INTER)
{
    __shared__ float tws[INPUT * INTER];  // 32 KB

    const int s = blockIdx.x;

    // Cooperative smem load of tw[s]
    {
        const float4* src = (const float4*)(tw + (size_t)s * INPUT * INTER);
        float4* dst = (float4*)tws;
        #pragma unroll 4
        for (int i = threadIdx.x; i < (INPUT * INTER) / 4; i += 256)
            dst[i] = src[i];
    }
    __syncthreads();

    const int warp = threadIdx.x >> 5;
    const int lane = threadIdx.x & 31;
    const int j0 = lane * 2;

    const int per = (NROWS + gridDim.y - 1) / gridDim.y;
    const int r0 = blockIdx.y * per;
    int r1 = r0 + per; if (r1 > NROWS) r1 = NROWS;

    for (int r = r0 + warp; r < r1; r += 8) {
        // Uniform across the warp (all lanes same r) -> no divergence
        if (tc[r] != s) continue;
        if (mask[r] == 0) continue;

        const int dcv = dc[r];
        const float* xr = x + (size_t)r * INPUT;

        float a0 = 0.0f, a1 = 0.0f;
        #pragma unroll
        for (int k = 0; k < INPUT; k += 4) {
            // broadcast load (same address across warp -> single L1 access)
            float4 xv = *(const float4*)(xr + k);
            float2 w0 = *(const float2*)(tws + (k + 0) * INTER + j0);
            float2 w1 = *(const float2*)(tws + (k + 1) * INTER + j0);
            float2 w2 = *(const float2*)(tws + (k + 2) * INTER + j0);
            float2 w3 = *(const float2*)(tws + (k + 3) * INTER + j0);
            a0 = fmaf(xv.x, w0.x, a0);  a1 = fmaf(xv.x, w0.y, a1);
            a0 = fmaf(xv.y, w1.x, a0);  a1 = fmaf(xv.y, w1.y, a1);
            a0 = fmaf(xv.z, w2.x, a0);  a1 = fmaf(xv.z, w2.y, a1);
            a0 = fmaf(xv.w, w3.x, a0);  a1 = fmaf(xv.w, w3.y, a1);
        }

        const int b = r / CDIM;
        float* up = g_u + (size_t)b * USTRIDE + dcv * INTER + j0;
        atomicAdd(up,     a0);
        atomicAdd(up + 1, a1);
    }
}

// ---------------------------------------------------------------------------
// K2: dense stage 2 + hidden path + sigmoid.
// grid.x = 64 CTAs, 4 batches each, 256 threads -> 2 outputs per thread.
//   out[b,hid] = sigmoid( sum_d u[b,d,:] @ dw[d][:,hid] + h[b,:] @ Hw[:,hid] )
// Weight matrices streamed through one 32KB smem buffer.
// ---------------------------------------------------------------------------
__global__ __launch_bounds__(256) void stage2_kernel(
    const float* __restrict__ h,    // (B, HIDDEN)
    const float* __restrict__ dw,   // (NSLOT, INTER, HIDDEN)
    const float* __restrict__ hw,   // (HIDDEN, HIDDEN)
    float* __restrict__ out)        // (B, HIDDEN)
{
    __shared__ float ws[INTER * HIDDEN];   // 32 KB, reused for Hw halves
    __shared__ float us[4 * INTER];        // u tile for 4 batches
    __shared__ float hs[4 * HIDDEN];       // h tile for 4 batches

    const int t = threadIdx.x;
    const int bbase = blockIdx.x * 4;
    const int b0  = t >> 7;     // 0..1
    const int hid = t & 127;

    // load h tile once
    for (int i = t; i < 4 * HIDDEN; i += 256)
        hs[i] = h[(size_t)bbase * HIDDEN + i];

    float acc0 = 0.0f, acc1 = 0.0f;

    for (int d = 0; d < NSLOT; d++) {
        __syncthreads();   // protect ws/us from previous iteration's readers
        us[t] = g_u[(size_t)(bbase + (t >> 6)) * USTRIDE + d * INTER + (t & 63)];
        {
            const float4* src = (const float4*)(dw + (size_t)d * INTER * HIDDEN);
            #pragma unroll 4
            for (int i = t; i < (INTER * HIDDEN) / 4; i += 256)
                ((float4*)ws)[i] = src[i];
        }
        __syncthreads();
        #pragma unroll
        for (int j = 0; j < INTER; j++) {
            float w = ws[j * HIDDEN + hid];          // conflict-free
            acc0 = fmaf(us[b0 * INTER + j],       w, acc0);  // broadcast
            acc1 = fmaf(us[(b0 + 2) * INTER + j], w, acc1);
        }
    }

    // hidden path: Hw streamed in two 64-row halves through ws
    for (int half = 0; half < 2; half++) {
        __syncthreads();
        {
            const float4* src = (const float4*)(hw + (size_t)half * 64 * HIDDEN);
            #pragma unroll 4
            for (int i = t; i < (64 * HIDDEN) / 4; i += 256)
                ((float4*)ws)[i] = src[i];
        }
        __syncthreads();
        #pragma unroll
        for (int j = 0; j < 64; j++) {
            float w = ws[j * HIDDEN + hid];
            int k = half * 64 + j;
            acc0 = fmaf(hs[b0 * HIDDEN + k],       w, acc0);
            acc1 = fmaf(hs[(b0 + 2) * HIDDEN + k], w, acc1);
        }
    }

    out[(size_t)(bbase + b0)     * HIDDEN + hid] = 1.0f / (1.0f + expf(-acc0));
    out[(size_t)(bbase + b0 + 2) * HIDDEN + hid] = 1.0f / (1.0f + expf(-acc1));
}

// ---------------------------------------------------------------------------
// kernel_launch: three stream-ordered launches (graph-capturable, alloc-free)
// ---------------------------------------------------------------------------
extern "C" void kernel_launch(void* const* d_in, const int* in_sizes, int n_in,
                              void* d_out, int out_size) {
    const float* x    = (const float*)d_in[0];
    const int*   tc   = (const int*)d_in[1];
    const int*   dc   = (const int*)d_in[2];
    const int*   mask = (const int*)d_in[3];
    const float* h    = (const float*)d_in[4];
    const float* tw   = (const float*)d_in[5];
    const float* dw   = (const float*)d_in[6];
    const float* hw   = (const float*)d_in[7];
    float*       out  = (float*)d_out;

    zero_u_kernel<<<88, 256>>>();
    stage1_kernel<<<dim3(11, 24), 256>>>(x, tc, dc, mask, tw);
    stage2_kernel<<<64, 256>>>(h, dw, hw, out);
}

// round 3
// speedup vs baseline: 1.1329x; 1.1329x over previous
#include <cuda_runtime.h>
#include <math.h>

#define NROWS   12800     // B*C
#define BATCH   256
#define CDIM    50
#define INPUT   128
#define INTER   64
#define HIDDEN  128
#define NSLOT   11
#define USTRIDE (NSLOT * INTER)   // 704
#define GRIDY   16
#define ROWS_PER_CTA (NROWS / GRIDY)   // 800

// Bucketed accumulator: u[b][dist_slot][j], fp32. 720 KB static device scratch.
__device__ float g_u[BATCH * NSLOT * INTER];

// ---------------------------------------------------------------------------
// K0: zero the accumulator. 45056 float4 = exactly 176 CTAs x 256 threads.
// ---------------------------------------------------------------------------
__global__ __launch_bounds__(256) void zero_u_kernel() {
    int i = blockIdx.x * 256 + threadIdx.x;
    ((float4*)g_u)[i] = make_float4(0.f, 0.f, 0.f, 0.f);
}

// ---------------------------------------------------------------------------
// K1: slot-major stage 1 with in-CTA compaction.
// grid = (11 slots, 16 row-chunks). Phase A: 256 threads scan 800 rows with
// coalesced tc/dc/mask loads, compact matching rows into smem list.
// Phase B: 8 warps drain the list; each warp computes t = x_row @ tw[s]
// (2 outputs/lane from smem weights) and atomicAdds into g_u[b][dc][*].
// ---------------------------------------------------------------------------
__global__ __launch_bounds__(256) void stage1_kernel(
    const float* __restrict__ x,          // (B,C,INPUT)
    const int* __restrict__ tc,           // (B,C)
    const int* __restrict__ dc,           // (B,C)
    const int* __restrict__ mask,         // (B,C) bool promoted to int32
    const float* __restrict__ tw)         // (NSLOT, INPUT, INTER)
{
    __shared__ float tws[INPUT * INTER];      // 32 KB
    __shared__ int   list[ROWS_PER_CTA];      // 3.2 KB: (dc<<16)|row
    __shared__ int   cnt;

    const int s = blockIdx.x;
    const int r0 = blockIdx.y * ROWS_PER_CTA;

    if (threadIdx.x == 0) cnt = 0;

    // Cooperative smem load of tw[s]
    {
        const float4* src = (const float4*)(tw + (size_t)s * INPUT * INTER);
        float4* dst = (float4*)tws;
        #pragma unroll 4
        for (int i = threadIdx.x; i < (INPUT * INTER) / 4; i += 256)
            dst[i] = src[i];
    }
    __syncthreads();

    // Phase A: coalesced scan + compaction
    #pragma unroll
    for (int i = threadIdx.x; i < ROWS_PER_CTA; i += 256) {
        int r = r0 + i;
        int t = tc[r];
        int m = mask[r];
        if (t == s && m != 0) {
            int pos = atomicAdd(&cnt, 1);
            list[pos] = (dc[r] << 16) | r;
        }
    }
    __syncthreads();

    const int n    = cnt;
    const int warp = threadIdx.x >> 5;
    const int lane = threadIdx.x & 31;
    const int j0   = lane * 2;

    // Phase B: compute surviving rows
    for (int i = warp; i < n; i += 8) {
        int e   = list[i];
        int r   = e & 0xFFFF;
        int dcv = e >> 16;
        const float* xr = x + (size_t)r * INPUT;

        float a0 = 0.0f, a1 = 0.0f;
        #pragma unroll
        for (int k = 0; k < INPUT; k += 4) {
            float4 xv = *(const float4*)(xr + k);   // broadcast across warp
            float2 w0 = *(const float2*)(tws + (k + 0) * INTER + j0);
            float2 w1 = *(const float2*)(tws + (k + 1) * INTER + j0);
            float2 w2 = *(const float2*)(tws + (k + 2) * INTER + j0);
            float2 w3 = *(const float2*)(tws + (k + 3) * INTER + j0);
            a0 = fmaf(xv.x, w0.x, a0);  a1 = fmaf(xv.x, w0.y, a1);
            a0 = fmaf(xv.y, w1.x, a0);  a1 = fmaf(xv.y, w1.y, a1);
            a0 = fmaf(xv.z, w2.x, a0);  a1 = fmaf(xv.z, w2.y, a1);
            a0 = fmaf(xv.w, w3.x, a0);  a1 = fmaf(xv.w, w3.y, a1);
        }

        const int b = r / CDIM;
        float* up = g_u + (size_t)b * USTRIDE + dcv * INTER + j0;
        atomicAdd(up,     a0);
        atomicAdd(up + 1, a1);
    }
}

// ---------------------------------------------------------------------------
// K2: dense stage 2 + hidden path + sigmoid.
// grid.x = 64 CTAs, 4 batches each, 256 threads -> 2 outputs per thread.
//   out[b,hid] = sigmoid( sum_d u[b,d,:] @ dw[d][:,hid] + h[b,:] @ Hw[:,hid] )
// ---------------------------------------------------------------------------
__global__ __launch_bounds__(256) void stage2_kernel(
    const float* __restrict__ h,    // (B, HIDDEN)
    const float* __restrict__ dw,   // (NSLOT, INTER, HIDDEN)
    const float* __restrict__ hw,   // (HIDDEN, HIDDEN)
    float* __restrict__ out)        // (B, HIDDEN)
{
    __shared__ float ws[INTER * HIDDEN];   // 32 KB, reused for Hw halves
    __shared__ float us[4 * INTER];        // u tile for 4 batches
    __shared__ float hs[4 * HIDDEN];       // h tile for 4 batches

    const int t = threadIdx.x;
    const int bbase = blockIdx.x * 4;
    const int b0  = t >> 7;     // 0..1
    const int hid = t & 127;

    for (int i = t; i < 4 * HIDDEN; i += 256)
        hs[i] = h[(size_t)bbase * HIDDEN + i];

    float acc0 = 0.0f, acc1 = 0.0f;

    for (int d = 0; d < NSLOT; d++) {
        __syncthreads();   // protect ws/us from previous iteration's readers
        us[t] = g_u[(size_t)(bbase + (t >> 6)) * USTRIDE + d * INTER + (t & 63)];
        {
            const float4* src = (const float4*)(dw + (size_t)d * INTER * HIDDEN);
            #pragma unroll 4
            for (int i = t; i < (INTER * HIDDEN) / 4; i += 256)
                ((float4*)ws)[i] = src[i];
        }
        __syncthreads();
        #pragma unroll
        for (int j = 0; j < INTER; j++) {
            float w = ws[j * HIDDEN + hid];          // conflict-free
            acc0 = fmaf(us[b0 * INTER + j],       w, acc0);  // broadcast
            acc1 = fmaf(us[(b0 + 2) * INTER + j], w, acc1);
        }
    }

    // hidden path: Hw streamed in two 64-row halves through ws
    for (int half = 0; half < 2; half++) {
        __syncthreads();
        {
            const float4* src = (const float4*)(hw + (size_t)half * 64 * HIDDEN);
            #pragma unroll 4
            for (int i = t; i < (64 * HIDDEN) / 4; i += 256)
                ((float4*)ws)[i] = src[i];
        }
        __syncthreads();
        #pragma unroll
        for (int j = 0; j < 64; j++) {
            float w = ws[j * HIDDEN + hid];
            int k = half * 64 + j;
            acc0 = fmaf(hs[b0 * HIDDEN + k],       w, acc0);
            acc1 = fmaf(hs[(b0 + 2) * HIDDEN + k], w, acc1);
        }
    }

    out[(size_t)(bbase + b0)     * HIDDEN + hid] = 1.0f / (1.0f + expf(-acc0));
    out[(size_t)(bbase + b0 + 2) * HIDDEN + hid] = 1.0f / (1.0f + expf(-acc1));
}

// ---------------------------------------------------------------------------
// kernel_launch: three stream-ordered launches (graph-capturable, alloc-free)
// ---------------------------------------------------------------------------
extern "C" void kernel_launch(void* const* d_in, const int* in_sizes, int n_in,
                              void* d_out, int out_size) {
    const float* x    = (const float*)d_in[0];
    const int*   tc   = (const int*)d_in[1];
    const int*   dc   = (const int*)d_in[2];
    const int*   mask = (const int*)d_in[3];
    const float* h    = (const float*)d_in[4];
    const float* tw   = (const float*)d_in[5];
    const float* dw   = (const float*)d_in[6];
    const float* hw   = (const float*)d_in[7];
    float*       out  = (float*)d_out;

    zero_u_kernel<<<176, 256>>>();
    stage1_kernel<<<dim3(NSLOT, GRIDY), 256>>>(x, tc, dc, mask, tw);
    stage2_kernel<<<64, 256>>>(h, dw, hw, out);
}